// round 15
// baseline (speedup 1.0000x reference)
#include <cuda_runtime.h>
#include <cuda_fp16.h>
#include <cstdint>

#define DD 1024
#define RR 4096
#define BB 32
#define NEG_INF_F (-1e9f)

// Scratch (no runtime device allocation allowed; static __device__ arrays OK)
__device__ float g_projv[BB * DD];
__device__ float g_scores[BB * RR];
__device__ __half g_Ah[(size_t)BB * RR * DD];   // 256MB: matrix pre-converted to fp16
// U fp16, packed per (k16-group, n): halves in order {0,1,8,9,2,3,10,11,4,5,12,13,6,7,14,15}
__device__ __half g_Uh2[DD * DD];

// ---------------------------------------------------------------------------
// helpers
// ---------------------------------------------------------------------------
__device__ __forceinline__ float fast_tanh(float x) {
    float y;
    asm("tanh.approx.f32 %0, %1;" : "=f"(y) : "f"(x));
    return y;
}

__device__ __forceinline__ void mma_fp16(float c[4], const uint32_t a[4], const uint32_t b[2]) {
    asm volatile(
        "mma.sync.aligned.m16n8k16.row.col.f32.f16.f16.f32 "
        "{%0,%1,%2,%3}, {%4,%5,%6,%7}, {%8,%9}, {%0,%1,%2,%3};\n"
        : "+f"(c[0]), "+f"(c[1]), "+f"(c[2]), "+f"(c[3])
        : "r"(a[0]), "r"(a[1]), "r"(a[2]), "r"(a[3]), "r"(b[0]), "r"(b[1]));
}

__device__ __forceinline__ void cp_async16(uint32_t sdst, const void* gsrc) {
    asm volatile("cp.async.cg.shared.global [%0], [%1], 16;\n" :: "r"(sdst), "l"(gsrc));
}

// ldmatrix x4 (b16): four 8x8 fp16 tiles == one m16n8k16 A fragment
__device__ __forceinline__ void ldsm_x4(uint32_t r[4], uint32_t saddr) {
    asm volatile("ldmatrix.sync.aligned.m8n8.x4.shared.b16 {%0,%1,%2,%3}, [%4];\n"
                 : "=r"(r[0]), "=r"(r[1]), "=r"(r[2]), "=r"(r[3]) : "r"(saddr));
}

// ---------------------------------------------------------------------------
// Kernel 0a: convert matrix fp32 -> fp16 (RN). One float4 per thread.
// ---------------------------------------------------------------------------
__global__ void convA_kernel(const float* __restrict__ M) {
    const size_t idx = (size_t)blockIdx.x * 256 + threadIdx.x;  // float4 index
    const float4 v = ((const float4*)M)[idx];
    __half2 h0 = __floats2half2_rn(v.x, v.y);
    __half2 h1 = __floats2half2_rn(v.z, v.w);
    uint2 o;
    o.x = *(uint32_t*)&h0;
    o.y = *(uint32_t*)&h1;
    ((uint2*)g_Ah)[idx] = o;
}

// ---------------------------------------------------------------------------
// Kernel 0b: pack U fp32 -> fp16 [k16-group][n][16] with fragment-order k.
// ---------------------------------------------------------------------------
__global__ void packU_kernel(const float* __restrict__ U) {
    const int id = blockIdx.x * 256 + threadIdx.x;   // 0..65535
    const int kg = id >> 10;
    const int n = id & 1023;
    const int ord[16] = {0, 1, 8, 9, 2, 3, 10, 11, 4, 5, 12, 13, 6, 7, 14, 15};
    __half h[16];
#pragma unroll
    for (int i = 0; i < 16; ++i)
        h[i] = __float2half_rn(U[(size_t)(kg * 16 + ord[i]) * DD + n]);
    uint4* dst = (uint4*)(g_Uh2 + (size_t)id * 16);
    dst[0] = *(uint4*)&h[0];
    dst[1] = *(uint4*)&h[8];
}

// ---------------------------------------------------------------------------
// Kernel 1: proj_v = vector @ W  (B x D) fp32, k-split x4 (proven)
// ---------------------------------------------------------------------------
__global__ void projv_kernel(const float* __restrict__ vec, const float* __restrict__ W) {
    __shared__ float vs[DD];
    __shared__ float part[4][64];
    const int b = blockIdx.y;
    const int n0 = blockIdx.x * 64;
    const int n = threadIdx.x & 63;
    const int kp = threadIdx.x >> 6;

    for (int k = threadIdx.x; k < DD; k += 256) vs[k] = vec[b * DD + k];
    __syncthreads();

    const float* Wp = W + (size_t)(kp * 256) * DD + n0 + n;
    const float* vp = vs + kp * 256;
    float acc = 0.0f;
#pragma unroll 8
    for (int k = 0; k < 256; ++k) acc = fmaf(vp[k], Wp[(size_t)k * DD], acc);
    part[kp][n] = acc;
    __syncthreads();
    if (kp == 0)
        g_projv[b * DD + n0 + n] = part[0][n] + part[1][n] + part[2][n] + part[3][n];
}

// ---------------------------------------------------------------------------
// Kernel 2: fused proj_m GEMM (fp16 m16n8k16) + tanh(+proj_v).v
// TWO CTAs PER SM: 128 threads, 4 warps (2M x 2N), warp tile 64x64.
// CTA tile 128(M) x 128(N-pass, x8), K-chunk 64 (x16/pass), THREE smem slots,
// prefetch depth 2 (wait_group 1): each chunk gets two compute windows to land.
// Per iter: wait<=1 -> sync -> issue(s+2) -> compute(s).
// Stage: A 128x64 fp16 XOR-swizzled (16KB) + B [4 k16][128 n][32B] (16KB) = 32KB.
// 3 stages + 128 score floats = 98816 B/CTA -> 2 CTAs co-resident.
// ---------------------------------------------------------------------------
#define STG_B  32768u
#define B_OFFB 16384u
#define NTOT   128           // 8 N-passes x 16 K64-chunks

__global__ __launch_bounds__(128, 2)
void fused_gemm_fp16(const float* __restrict__ vvec) {
    extern __shared__ __align__(128) float smem[];
    float* s_score = (float*)((char*)smem + 3 * STG_B);

    const int tid = threadIdx.x;
    const int warp = tid >> 5;
    const int lane = tid & 31;
    const int wm = warp & 1;       // 0..1  (64 rows each)
    const int wn = warp >> 1;      // 0..1  (64 cols each)
    const int g = lane >> 2;       // 0..7
    const int t = lane & 3;        // 0..3

    const int b = blockIdx.y;
    const int row0 = blockIdx.x * 128;

    s_score[tid] = 0.0f;

    const __half* Ag = g_Ah + ((size_t)b * RR + row0) * DD;
    const uint32_t sb = (uint32_t)__cvta_generic_to_shared(smem);

    // ldmatrix lane roles
    const int r7 = lane & 7;
    const int mh = lane >> 4;                      // col 16B-half (k +8)
    const int mrow = ((lane >> 3) & 1) * 8 + r7;   // row-in-16-tile

    // A cp.async mapping: rows ar+16i (i<8), 16B chunk ac (8 halves)
    const int ar = tid >> 3, ac = tid & 7;         // ar 0..15
    const uint32_t a_sw = (uint32_t)(ar & 7);      // row&7 invariant under +16

    auto issue_loads = [&](int sl) {
        const uint32_t slot = (uint32_t)(sl % 3);
        const int kt = sl & 15;
        const int n0 = (sl >> 4) * 128;
        const uint32_t abase = sb + slot * STG_B;
        const uint32_t bbase = abase + B_OFFB;
        const __half* asrc = Ag + (size_t)ar * DD + kt * 64 + ac * 8;
#pragma unroll
        for (int i = 0; i < 8; ++i) {
            const int row = ar + i * 16;
            cp_async16(abase + (uint32_t)(row * 128) + ((((uint32_t)ac) ^ a_sw) << 4),
                       asrc + (size_t)i * 16 * DD);
        }
        // B: 1024 16B-chunks; chunk c: kg_l=c>>8, n=(c>>1)&127, half=c&1
#pragma unroll
        for (int i = 0; i < 8; ++i) {
            const int c = i * 128 + tid;
            const int kg_l = c >> 8;
            const int n = (c >> 1) & 127;
            const int half = c & 1;
            cp_async16(bbase + (uint32_t)c * 16u,
                       g_Uh2 + ((size_t)(kt * 4 + kg_l) * DD + n0 + n) * 16 + half * 8);
        }
    };

    // prefetch chunks 0,1 into slots 0,1 (two groups)
    issue_loads(0);
    asm volatile("cp.async.commit_group;\n");
    issue_loads(1);
    asm volatile("cp.async.commit_group;\n");

    float acc[4][8][4];
#pragma unroll
    for (int i = 0; i < 4; ++i)
#pragma unroll
        for (int j = 0; j < 8; ++j)
#pragma unroll
            for (int q = 0; q < 4; ++q) acc[i][j][q] = 0.0f;

    const float* pv = g_projv + b * DD;

    for (int s = 0; s < NTOT; ++s) {
        // chunk s resident; allow the youngest group (s+1) to stay in flight
        if (s + 2 < NTOT)
            asm volatile("cp.async.wait_group 1;\n");
        else
            asm volatile("cp.async.wait_group 0;\n");
        __syncthreads();                            // slot (s+2)%3 readers done

        if (s + 2 < NTOT) {                         // issue chunk s+2
            issue_loads(s + 2);
            asm volatile("cp.async.commit_group;\n");
        }

        const uint32_t slot = (uint32_t)(s % 3);
        const uint32_t Ab32 = sb + slot * STG_B;
        const __half* Bh = (const __half*)((const char*)smem + slot * STG_B + B_OFFB);

        uint32_t afr[2][4][4];
        uint32_t bfr[2][8][2];
        auto load_frags = [&](int ks, int buf) {
            const uint32_t cx = (uint32_t)((2 * ks + mh) ^ r7) << 4;
#pragma unroll
            for (int i = 0; i < 4; ++i) {
                const int row = wm * 64 + i * 16 + mrow;
                ldsm_x4(afr[buf][i], Ab32 + (uint32_t)(row * 128) + cx);
            }
            const __half* bks = Bh + ks * 2048 + t * 4;  // ks*(128 cols * 16h)
#pragma unroll
            for (int j = 0; j < 8; ++j) {
                const uint2 p = *(const uint2*)(bks + (wn * 64 + j * 8 + g) * 16);
                bfr[buf][j][0] = p.x;   // k = 2t, 2t+1
                bfr[buf][j][1] = p.y;   // k = 2t+8, 2t+9
            }
        };

        load_frags(0, 0);
#pragma unroll
        for (int ks = 0; ks < 4; ++ks) {
            const int cur = ks & 1;
            if (ks < 3) load_frags(ks + 1, cur ^ 1);
#pragma unroll
            for (int i = 0; i < 4; ++i)
#pragma unroll
                for (int j = 0; j < 8; ++j)
                    mma_fp16(acc[i][j], afr[cur][i], bfr[cur][j]);
        }

        if ((s & 15) == 15) {
            // epilogue for this 128-col pass: tanh(acc + pv) . v
            const int n0 = (s >> 4) * 128;
            float ps[4][2];
#pragma unroll
            for (int i = 0; i < 4; ++i) { ps[i][0] = 0.0f; ps[i][1] = 0.0f; }
#pragma unroll
            for (int j = 0; j < 8; ++j) {
                const int cb = n0 + wn * 64 + j * 8 + 2 * t;
                const float2 pvv = *(const float2*)(pv + cb);
                const float2 vv = *(const float2*)(vvec + cb);
#pragma unroll
                for (int i = 0; i < 4; ++i) {
                    ps[i][0] = fmaf(fast_tanh(acc[i][j][0] + pvv.x), vv.x, ps[i][0]);
                    ps[i][0] = fmaf(fast_tanh(acc[i][j][1] + pvv.y), vv.y, ps[i][0]);
                    ps[i][1] = fmaf(fast_tanh(acc[i][j][2] + pvv.x), vv.x, ps[i][1]);
                    ps[i][1] = fmaf(fast_tanh(acc[i][j][3] + pvv.y), vv.y, ps[i][1]);
                    acc[i][j][0] = 0.0f; acc[i][j][1] = 0.0f;
                    acc[i][j][2] = 0.0f; acc[i][j][3] = 0.0f;
                }
            }
#pragma unroll
            for (int i = 0; i < 4; ++i)
#pragma unroll
                for (int h = 0; h < 2; ++h) {
                    float x = ps[i][h];
                    x += __shfl_xor_sync(0xffffffffu, x, 1);
                    x += __shfl_xor_sync(0xffffffffu, x, 2);
                    if (t == 0) atomicAdd(&s_score[wm * 64 + i * 16 + h * 8 + g], x);
                }
        }
    }

    __syncthreads();
    g_scores[(size_t)b * RR + row0 + tid] = s_score[tid];
}

// ---------------------------------------------------------------------------
// Kernel 3: masked softmax over R per batch. grid (B), 256 threads.
// ---------------------------------------------------------------------------
__global__ void softmax_kernel(const int* __restrict__ mask, float* __restrict__ out) {
    const int b = blockIdx.x;
    __shared__ float red[256];
    const float* s = g_scores + (size_t)b * RR;
    const int* m = mask + (size_t)b * RR;

    float l[16];
    float lmax = -3.0e38f;
#pragma unroll
    for (int i = 0; i < 16; ++i) {
        const int r = threadIdx.x + i * 256;
        l[i] = (m[r] > 0) ? s[r] : NEG_INF_F;
        lmax = fmaxf(lmax, l[i]);
    }
    red[threadIdx.x] = lmax;
    __syncthreads();
    for (int off = 128; off > 0; off >>= 1) {
        if (threadIdx.x < off) red[threadIdx.x] = fmaxf(red[threadIdx.x], red[threadIdx.x + off]);
        __syncthreads();
    }
    const float gmax = red[0];
    __syncthreads();

    float e[16];
    float lsum = 0.0f;
#pragma unroll
    for (int i = 0; i < 16; ++i) {
        e[i] = __expf(l[i] - gmax);
        lsum += e[i];
    }
    red[threadIdx.x] = lsum;
    __syncthreads();
    for (int off = 128; off > 0; off >>= 1) {
        if (threadIdx.x < off) red[threadIdx.x] += red[threadIdx.x + off];
        __syncthreads();
    }
    const float inv = __frcp_rn(red[0]);
#pragma unroll
    for (int i = 0; i < 16; ++i)
        out[(size_t)b * RR + threadIdx.x + i * 256] = e[i] * inv;
}

// ---------------------------------------------------------------------------
// launch
// ---------------------------------------------------------------------------
extern "C" void kernel_launch(void* const* d_in, const int* in_sizes, int n_in,
                              void* d_out, int out_size) {
    (void)in_sizes; (void)n_in; (void)out_size;
    const float* vec    = (const float*)d_in[0];  // (32,1024)
    const float* matrix = (const float*)d_in[1];  // (32,4096,1024)
    const int*   mask   = (const int*)  d_in[2];  // (32,4096)
    const float* W      = (const float*)d_in[3];  // (1024,1024)
    const float* U      = (const float*)d_in[4];  // (1024,1024)
    const float* v      = (const float*)d_in[5];  // (1024,1)
    float* out = (float*)d_out;                   // (32,4096)

    const int SMEM = 3 * STG_B + 128 * 4;  // 98816 B
    static int configured = 0;
    if (!configured) {
        cudaFuncSetAttribute(fused_gemm_fp16, cudaFuncAttributeMaxDynamicSharedMemorySize, SMEM);
        configured = 1;
    }

    convA_kernel<<<131072, 256>>>(matrix);
    packU_kernel<<<256, 256>>>(U);
    projv_kernel<<<dim3(DD / 64, BB), 256>>>(vec, W);
    fused_gemm_fp16<<<dim3(RR / 128, BB), 128, SMEM>>>(v);
    softmax_kernel<<<BB, 256>>>(mask, out);
}

// round 16
// speedup vs baseline: 1.0535x; 1.0535x over previous
#include <cuda_runtime.h>
#include <cuda_fp16.h>
#include <cstdint>

#define DD 1024
#define RR 4096
#define BB 32
#define NEG_INF_F (-1e9f)

// Scratch (no runtime device allocation allowed; static __device__ arrays OK)
__device__ float g_projv[BB * DD];
__device__ float g_scores[BB * RR];
__device__ __half g_Ah[(size_t)BB * RR * DD];   // 256MB: matrix pre-converted to fp16
// U fp16, packed per (k16-group, n): halves in order {0,1,8,9,2,3,10,11,4,5,12,13,6,7,14,15}
__device__ __half g_Uh2[DD * DD];

// ---------------------------------------------------------------------------
// helpers
// ---------------------------------------------------------------------------
__device__ __forceinline__ float fast_tanh(float x) {
    float y;
    asm("tanh.approx.f32 %0, %1;" : "=f"(y) : "f"(x));
    return y;
}

__device__ __forceinline__ void mma_fp16(float c[4], const uint32_t a[4], const uint32_t b[2]) {
    asm volatile(
        "mma.sync.aligned.m16n8k16.row.col.f32.f16.f16.f32 "
        "{%0,%1,%2,%3}, {%4,%5,%6,%7}, {%8,%9}, {%0,%1,%2,%3};\n"
        : "+f"(c[0]), "+f"(c[1]), "+f"(c[2]), "+f"(c[3])
        : "r"(a[0]), "r"(a[1]), "r"(a[2]), "r"(a[3]), "r"(b[0]), "r"(b[1]));
}

__device__ __forceinline__ void cp_async16(uint32_t sdst, const void* gsrc) {
    asm volatile("cp.async.cg.shared.global [%0], [%1], 16;\n" :: "r"(sdst), "l"(gsrc));
}

// ldmatrix x4 (b16): four 8x8 fp16 tiles == one m16n8k16 A fragment
__device__ __forceinline__ void ldsm_x4(uint32_t r[4], uint32_t saddr) {
    asm volatile("ldmatrix.sync.aligned.m8n8.x4.shared.b16 {%0,%1,%2,%3}, [%4];\n"
                 : "=r"(r[0]), "=r"(r[1]), "=r"(r[2]), "=r"(r[3]) : "r"(saddr));
}

// ---------------------------------------------------------------------------
// Kernel 0a: convert matrix fp32 -> fp16 (RN). One float4 per thread.
// ---------------------------------------------------------------------------
__global__ void convA_kernel(const float* __restrict__ M) {
    const size_t idx = (size_t)blockIdx.x * 256 + threadIdx.x;  // float4 index
    const float4 v = ((const float4*)M)[idx];
    __half2 h0 = __floats2half2_rn(v.x, v.y);
    __half2 h1 = __floats2half2_rn(v.z, v.w);
    uint2 o;
    o.x = *(uint32_t*)&h0;
    o.y = *(uint32_t*)&h1;
    ((uint2*)g_Ah)[idx] = o;
}

// ---------------------------------------------------------------------------
// Kernel 0b: pack U fp32 -> fp16 [k16-group][n][16] with fragment-order k.
// ---------------------------------------------------------------------------
__global__ void packU_kernel(const float* __restrict__ U) {
    const int id = blockIdx.x * 256 + threadIdx.x;   // 0..65535
    const int kg = id >> 10;
    const int n = id & 1023;
    const int ord[16] = {0, 1, 8, 9, 2, 3, 10, 11, 4, 5, 12, 13, 6, 7, 14, 15};
    __half h[16];
#pragma unroll
    for (int i = 0; i < 16; ++i)
        h[i] = __float2half_rn(U[(size_t)(kg * 16 + ord[i]) * DD + n]);
    uint4* dst = (uint4*)(g_Uh2 + (size_t)id * 16);
    dst[0] = *(uint4*)&h[0];
    dst[1] = *(uint4*)&h[8];
}

// ---------------------------------------------------------------------------
// Kernel 0c: zero the score accumulator (atomically accumulated per N-pass)
// ---------------------------------------------------------------------------
__global__ void zeroS_kernel() {
    g_scores[blockIdx.x * 1024 + threadIdx.x] = 0.0f;
}

// ---------------------------------------------------------------------------
// Kernel 1: proj_v = vector @ W  (B x D) fp32, k-split x4 (proven)
// ---------------------------------------------------------------------------
__global__ void projv_kernel(const float* __restrict__ vec, const float* __restrict__ W) {
    __shared__ float vs[DD];
    __shared__ float part[4][64];
    const int b = blockIdx.y;
    const int n0 = blockIdx.x * 64;
    const int n = threadIdx.x & 63;
    const int kp = threadIdx.x >> 6;

    for (int k = threadIdx.x; k < DD; k += 256) vs[k] = vec[b * DD + k];
    __syncthreads();

    const float* Wp = W + (size_t)(kp * 256) * DD + n0 + n;
    const float* vp = vs + kp * 256;
    float acc = 0.0f;
#pragma unroll 8
    for (int k = 0; k < 256; ++k) acc = fmaf(vp[k], Wp[(size_t)k * DD], acc);
    part[kp][n] = acc;
    __syncthreads();
    if (kp == 0)
        g_projv[b * DD + n0 + n] = part[0][n] + part[1][n] + part[2][n] + part[3][n];
}

// ---------------------------------------------------------------------------
// Kernel 2: fused proj_m GEMM (fp16 m16n8k16) + tanh(+proj_v).v
// WORK-SPLIT for wave efficiency: one CTA = one (row-tile, N-pass, batch) unit
// = 16 K64-chunks. grid (32x8, 32) = 8192 CTAs -> 27.7 waves of 296, 98.8% util
// (was 1024 CTAs = 3.46 waves, 86.5%). Partial row-sums atomicAdd'ed to global.
// Inner loop byte-identical to R14: 128 threads, 4 warps (2M x 2N), warp tile
// 64x64, 2-stage double buffer, one sync/chunk, 2 CTAs/SM.
// ---------------------------------------------------------------------------
#define STG_B  32768u
#define B_OFFB 16384u
#define NTOT   16            // 16 K64-chunks per work unit

__global__ __launch_bounds__(128, 2)
void fused_gemm_fp16(const float* __restrict__ vvec) {
    extern __shared__ __align__(128) float smem[];
    float* s_score = (float*)((char*)smem + 2 * STG_B);

    const int tid = threadIdx.x;
    const int warp = tid >> 5;
    const int lane = tid & 31;
    const int wm = warp & 1;       // 0..1  (64 rows each)
    const int wn = warp >> 1;      // 0..1  (64 cols each)
    const int g = lane >> 2;       // 0..7
    const int t = lane & 3;        // 0..3

    const int b = blockIdx.y;
    const int row0 = (blockIdx.x & 31) * 128;
    const int n0 = (blockIdx.x >> 5) * 128;      // this CTA's N-pass

    s_score[tid] = 0.0f;

    const __half* Ag = g_Ah + ((size_t)b * RR + row0) * DD;
    const uint32_t sb = (uint32_t)__cvta_generic_to_shared(smem);

    // ldmatrix lane roles
    const int r7 = lane & 7;
    const int mh = lane >> 4;                      // col 16B-half (k +8)
    const int mrow = ((lane >> 3) & 1) * 8 + r7;   // row-in-16-tile

    // A cp.async mapping: rows ar+16i (i<8), 16B chunk ac (8 halves)
    const int ar = tid >> 3, ac = tid & 7;         // ar 0..15
    const uint32_t a_sw = (uint32_t)(ar & 7);      // row&7 invariant under +16

    auto issue_loads = [&](int kt) {
        const uint32_t slot = (uint32_t)(kt & 1);
        const uint32_t abase = sb + slot * STG_B;
        const uint32_t bbase = abase + B_OFFB;
        const __half* asrc = Ag + (size_t)ar * DD + kt * 64 + ac * 8;
#pragma unroll
        for (int i = 0; i < 8; ++i) {
            const int row = ar + i * 16;
            cp_async16(abase + (uint32_t)(row * 128) + ((((uint32_t)ac) ^ a_sw) << 4),
                       asrc + (size_t)i * 16 * DD);
        }
        // B: 1024 16B-chunks; chunk c: kg_l=c>>8, n=(c>>1)&127, half=c&1
#pragma unroll
        for (int i = 0; i < 8; ++i) {
            const int c = i * 128 + tid;
            const int kg_l = c >> 8;
            const int n = (c >> 1) & 127;
            const int half = c & 1;
            cp_async16(bbase + (uint32_t)c * 16u,
                       g_Uh2 + ((size_t)(kt * 4 + kg_l) * DD + n0 + n) * 16 + half * 8);
        }
    };

    // prefetch chunk 0 into slot 0
    issue_loads(0);
    asm volatile("cp.async.commit_group;\n");

    float acc[4][8][4];
#pragma unroll
    for (int i = 0; i < 4; ++i)
#pragma unroll
        for (int j = 0; j < 8; ++j)
#pragma unroll
            for (int q = 0; q < 4; ++q) acc[i][j][q] = 0.0f;

    const float* pv = g_projv + b * DD;

    for (int s = 0; s < NTOT; ++s) {
        asm volatile("cp.async.wait_group 0;\n");   // chunk s resident
        __syncthreads();                            // slot (s+1)&1 readers done

        if (s + 1 < NTOT) {                         // issue chunk s+1
            issue_loads(s + 1);
            asm volatile("cp.async.commit_group;\n");
        }

        const uint32_t slot = (uint32_t)(s & 1);
        const uint32_t Ab32 = sb + slot * STG_B;
        const __half* Bh = (const __half*)((const char*)smem + slot * STG_B + B_OFFB);

        uint32_t afr[2][4][4];
        uint32_t bfr[2][8][2];
        auto load_frags = [&](int ks, int buf) {
            const uint32_t cx = (uint32_t)((2 * ks + mh) ^ r7) << 4;
#pragma unroll
            for (int i = 0; i < 4; ++i) {
                const int row = wm * 64 + i * 16 + mrow;
                ldsm_x4(afr[buf][i], Ab32 + (uint32_t)(row * 128) + cx);
            }
            const __half* bks = Bh + ks * 2048 + t * 4;  // ks*(128 cols * 16h)
#pragma unroll
            for (int j = 0; j < 8; ++j) {
                const uint2 p = *(const uint2*)(bks + (wn * 64 + j * 8 + g) * 16);
                bfr[buf][j][0] = p.x;   // k = 2t, 2t+1
                bfr[buf][j][1] = p.y;   // k = 2t+8, 2t+9
            }
        };

        load_frags(0, 0);
#pragma unroll
        for (int ks = 0; ks < 4; ++ks) {
            const int cur = ks & 1;
            if (ks < 3) load_frags(ks + 1, cur ^ 1);
#pragma unroll
            for (int i = 0; i < 4; ++i)
#pragma unroll
                for (int j = 0; j < 8; ++j)
                    mma_fp16(acc[i][j], afr[cur][i], bfr[cur][j]);
        }
    }

    // epilogue (once per work unit): tanh(acc + pv) . v over this 128-col pass
    {
        float ps[4][2];
#pragma unroll
        for (int i = 0; i < 4; ++i) { ps[i][0] = 0.0f; ps[i][1] = 0.0f; }
#pragma unroll
        for (int j = 0; j < 8; ++j) {
            const int cb = n0 + wn * 64 + j * 8 + 2 * t;
            const float2 pvv = *(const float2*)(pv + cb);
            const float2 vv = *(const float2*)(vvec + cb);
#pragma unroll
            for (int i = 0; i < 4; ++i) {
                ps[i][0] = fmaf(fast_tanh(acc[i][j][0] + pvv.x), vv.x, ps[i][0]);
                ps[i][0] = fmaf(fast_tanh(acc[i][j][1] + pvv.y), vv.y, ps[i][0]);
                ps[i][1] = fmaf(fast_tanh(acc[i][j][2] + pvv.x), vv.x, ps[i][1]);
                ps[i][1] = fmaf(fast_tanh(acc[i][j][3] + pvv.y), vv.y, ps[i][1]);
            }
        }
#pragma unroll
        for (int i = 0; i < 4; ++i)
#pragma unroll
            for (int h = 0; h < 2; ++h) {
                float x = ps[i][h];
                x += __shfl_xor_sync(0xffffffffu, x, 1);
                x += __shfl_xor_sync(0xffffffffu, x, 2);
                if (t == 0) atomicAdd(&s_score[wm * 64 + i * 16 + h * 8 + g], x);
            }
    }

    __syncthreads();
    atomicAdd(&g_scores[(size_t)b * RR + row0 + tid], s_score[tid]);
}

// ---------------------------------------------------------------------------
// Kernel 3: masked softmax over R per batch. grid (B), 256 threads.
// ---------------------------------------------------------------------------
__global__ void softmax_kernel(const int* __restrict__ mask, float* __restrict__ out) {
    const int b = blockIdx.x;
    __shared__ float red[256];
    const float* s = g_scores + (size_t)b * RR;
    const int* m = mask + (size_t)b * RR;

    float l[16];
    float lmax = -3.0e38f;
#pragma unroll
    for (int i = 0; i < 16; ++i) {
        const int r = threadIdx.x + i * 256;
        l[i] = (m[r] > 0) ? s[r] : NEG_INF_F;
        lmax = fmaxf(lmax, l[i]);
    }
    red[threadIdx.x] = lmax;
    __syncthreads();
    for (int off = 128; off > 0; off >>= 1) {
        if (threadIdx.x < off) red[threadIdx.x] = fmaxf(red[threadIdx.x], red[threadIdx.x + off]);
        __syncthreads();
    }
    const float gmax = red[0];
    __syncthreads();

    float e[16];
    float lsum = 0.0f;
#pragma unroll
    for (int i = 0; i < 16; ++i) {
        e[i] = __expf(l[i] - gmax);
        lsum += e[i];
    }
    red[threadIdx.x] = lsum;
    __syncthreads();
    for (int off = 128; off > 0; off >>= 1) {
        if (threadIdx.x < off) red[threadIdx.x] += red[threadIdx.x + off];
        __syncthreads();
    }
    const float inv = __frcp_rn(red[0]);
#pragma unroll
    for (int i = 0; i < 16; ++i)
        out[(size_t)b * RR + threadIdx.x + i * 256] = e[i] * inv;
}

// ---------------------------------------------------------------------------
// launch
// ---------------------------------------------------------------------------
extern "C" void kernel_launch(void* const* d_in, const int* in_sizes, int n_in,
                              void* d_out, int out_size) {
    (void)in_sizes; (void)n_in; (void)out_size;
    const float* vec    = (const float*)d_in[0];  // (32,1024)
    const float* matrix = (const float*)d_in[1];  // (32,4096,1024)
    const int*   mask   = (const int*)  d_in[2];  // (32,4096)
    const float* W      = (const float*)d_in[3];  // (1024,1024)
    const float* U      = (const float*)d_in[4];  // (1024,1024)
    const float* v      = (const float*)d_in[5];  // (1024,1)
    float* out = (float*)d_out;                   // (32,4096)

    const int SMEM = 2 * STG_B + 128 * 4;  // 66048 B
    static int configured = 0;
    if (!configured) {
        cudaFuncSetAttribute(fused_gemm_fp16, cudaFuncAttributeMaxDynamicSharedMemorySize, SMEM);
        configured = 1;
    }

    convA_kernel<<<131072, 256>>>(matrix);
    packU_kernel<<<256, 256>>>(U);
    zeroS_kernel<<<128, 1024>>>();
    projv_kernel<<<dim3(DD / 64, BB), 256>>>(vec, W);
    fused_gemm_fp16<<<dim3(256, BB), 128, SMEM>>>(v);
    softmax_kernel<<<BB, 256>>>(mask, out);
}